// round 5
// baseline (speedup 1.0000x reference)
#include <cuda_runtime.h>
#include <cuda_bf16.h>
#include <cstdint>
#include <cstddef>

#define DEV_INLINE __device__ __forceinline__
typedef unsigned long long u64;

// B=8, C=64, S=256, WS=32, P=4, HEADS=8, DH=64
constexpr int NTOK = 32768;      // 512 windows * 64 tokens
constexpr int TOKD = 1024;
constexpr int QKVD = 1536;
constexpr int INNERD = 512;

// ---- static scratch ----
__device__ float g_tokens[(size_t)NTOK * TOKD];
__device__ float g_qkv[(size_t)NTOK * QKVD];
__device__ float g_o[(size_t)NTOK * INNERD];
__device__ float g_wqkv[(size_t)TOKD * QKVD];
__device__ float g_wout[(size_t)INNERD * TOKD];
__device__ float g_bias[TOKD];

DEV_INLINE float tf32r(float v) {
    uint32_t u; asm("cvt.rna.tf32.f32 %0, %1;" : "=r"(u) : "f"(v));
    return __uint_as_float(u);
}
// k-interleave within each 8-block: pos(k) = (k&3)*2 + ((k>>2)&1)
DEV_INLINE int pk8(int k) { return (k & ~7) | ((k & 3) * 2 + ((k >> 2) & 1)); }

DEV_INLINE void mma8(float* d, const uint32_t* a, const uint32_t* b) {
    asm volatile("mma.sync.aligned.m16n8k8.row.col.f32.tf32.tf32.f32 "
        "{%0,%1,%2,%3}, {%4,%5,%6,%7}, {%8,%9}, {%0,%1,%2,%3};"
        : "+f"(d[0]), "+f"(d[1]), "+f"(d[2]), "+f"(d[3])
        : "r"(a[0]), "r"(a[1]), "r"(a[2]), "r"(a[3]), "r"(b[0]), "r"(b[1]));
}
DEV_INLINE void cp16(float* dst, const float* src) {
    uint32_t a = (uint32_t)__cvta_generic_to_shared(dst);
    asm volatile("cp.async.ca.shared.global [%0], [%1], 16;" :: "r"(a), "l"(src));
}
DEV_INLINE void fma2(u64& d, u64 a, u64 b) {
    asm("fma.rn.f32x2 %0, %1, %2, %0;" : "+l"(d) : "l"(a), "l"(b));
}
DEV_INLINE u64 pk2(float x, float y) {
    u64 r; asm("mov.b64 %0, {%1,%2};" : "=l"(r) : "r"(__float_as_uint(x)), "r"(__float_as_uint(y)));
    return r;
}
DEV_INLINE void upk2(u64 v, float& x, float& y) {
    uint32_t a, b; asm("mov.b64 {%0,%1}, %2;" : "=r"(a), "=r"(b) : "l"(v));
    x = __uint_as_float(a); y = __uint_as_float(b);
}

// ---- weight permutation: d' = c*16 + p1*4 + p2 ; orig d = (p1*4+p2)*64 + c ----
// rows stored at pk8(k) for the GEMM k-interleave
__global__ void perm_wqkv_k(const float* __restrict__ w) {
    int dp = blockIdx.x;                       // d' 0..1023
    int src = (dp & 15) * 64 + (dp >> 4);
    float4 v = ((const float4*)(w + (size_t)src * QKVD))[threadIdx.x];  // 384 thr
    v.x = tf32r(v.x); v.y = tf32r(v.y); v.z = tf32r(v.z); v.w = tf32r(v.w);
    ((float4*)(g_wqkv + (size_t)pk8(dp) * QKVD))[threadIdx.x] = v;
}
__global__ void perm_wout_k(const float* __restrict__ w, const float* __restrict__ b) {
    int e = blockIdx.x;                        // 0..511
    int dp = threadIdx.x;                      // 0..1023
    int src = (dp & 15) * 64 + (dp >> 4);
    g_wout[(size_t)pk8(e) * TOKD + dp] = tf32r(w[(size_t)e * TOKD + src]);
    if (e == 0) g_bias[dp] = b[src];
}

// ---- gather: x[b,c,h,w] -> tokens[win*64+t][pk8(d')] (tf32-rounded) ----
__global__ void gather_k(const float* __restrict__ x) {
    int blk = blockIdx.x;                // 2048 = b*256 + h
    int b = blk >> 8, h = blk & 255;
    int tid = threadIdx.x;               // 256
    int w4 = tid & 63, c0 = tid >> 6;
    int h1 = h >> 5, hh = h & 31, nh_i = hh >> 2, p1 = hh & 3;
    int w1 = w4 >> 3, nw_j = w4 & 7;
    int win = b * 64 + h1 * 8 + w1;
    int t = nh_i * 8 + nw_j;
    // d' = c*16 + p1*4 + p2 -> storage (c*2 + (p1>>1))*8 + p2*2 + (p1&1)
    int off = p1 & 1, blk8 = (p1 >> 1) * 8;
    size_t drow = ((size_t)win * 64 + t) * TOKD + blk8 + off;
    size_t sbase = (((size_t)b * 64) * 256 + h) * 256 + w4 * 4;
#pragma unroll
    for (int i = 0; i < 16; i++) {
        int c = c0 * 16 + i;
        float4 v = *(const float4*)&x[sbase + (size_t)c * 65536];
        float* d = &g_tokens[drow + (size_t)c * 16];
        d[0] = tf32r(v.x); d[2] = tf32r(v.y); d[4] = tf32r(v.z); d[6] = tf32r(v.w);
    }
}

// scatter index for fused out-GEMM epilogue: (row=token, col=d') -> x layout
DEV_INLINE size_t scat_idx(int row, int col) {
    int win = row >> 6, t = row & 63;
    int b = win >> 6, rem = win & 63;
    int hh = ((rem >> 3) << 5) + ((t >> 3) << 2) + ((col >> 2) & 3);
    int ww = ((rem & 7) << 5) + ((t & 7) << 2) + (col & 3);
    int c = col >> 4;
    return ((((size_t)(b * 64 + c) << 8) + hh) << 8) + ww;
}

// ---- tf32 GEMM: 128x128 tile, K-step 16, double-buffered, 256 thr, 8 warps ----
// A columns & B rows are pk8-interleaved -> A frag pair (k,k+4) contiguous (LDS.64)
constexpr int AST = 24;    // A smem stride (16 + 8 pad): conflict-free float2 frags
constexpr int BST = 132;   // B smem stride (128 + 4): conflict-free scalar frags
template<int K, int N, int MODE>
__global__ void __launch_bounds__(256) gemm_tf32_k(float* __restrict__ outp) {
    __shared__ float As[2][128 * AST];
    __shared__ float Bs[2][16 * BST];
    const float* A = (MODE == 0) ? g_tokens : g_o;
    const float* B = (MODE == 0) ? g_wqkv : g_wout;

    const int tid = threadIdx.x, warp = tid >> 5, lane = tid & 31;
    const int wm = warp >> 2, wn = warp & 3;       // 2 x 4 warps, 64x32 tiles
    const int tm = blockIdx.y * 128, tn = blockIdx.x * 128;
    const int r0 = lane >> 2, kk = lane & 3;

    const int ar = tid >> 2, ak4 = tid & 3;
    const int br = tid >> 5, bn4 = tid & 31;

    float acc[4][4][4];
#pragma unroll
    for (int mi = 0; mi < 4; mi++)
#pragma unroll
        for (int ni = 0; ni < 4; ni++)
#pragma unroll
            for (int j = 0; j < 4; j++) acc[mi][ni][j] = 0.f;

    constexpr int KT = K / 16;
    cp16(&As[0][ar * AST + ak4 * 4], &A[(size_t)(tm + ar) * K + ak4 * 4]);
    cp16(&As[0][(ar + 64) * AST + ak4 * 4], &A[(size_t)(tm + ar + 64) * K + ak4 * 4]);
    cp16(&Bs[0][br * BST + bn4 * 4], &B[(size_t)br * N + tn + bn4 * 4]);
    cp16(&Bs[0][(br + 8) * BST + bn4 * 4], &B[(size_t)(br + 8) * N + tn + bn4 * 4]);
    asm volatile("cp.async.commit_group;");

    for (int kt = 0; kt < KT; kt++) {
        if (kt + 1 < KT) {
            const int k0 = (kt + 1) * 16, bf = (kt + 1) & 1;
            cp16(&As[bf][ar * AST + ak4 * 4], &A[(size_t)(tm + ar) * K + k0 + ak4 * 4]);
            cp16(&As[bf][(ar + 64) * AST + ak4 * 4], &A[(size_t)(tm + ar + 64) * K + k0 + ak4 * 4]);
            cp16(&Bs[bf][br * BST + bn4 * 4], &B[(size_t)(k0 + br) * N + tn + bn4 * 4]);
            cp16(&Bs[bf][(br + 8) * BST + bn4 * 4], &B[(size_t)(k0 + br + 8) * N + tn + bn4 * 4]);
            asm volatile("cp.async.commit_group;");
            asm volatile("cp.async.wait_group 1;");
        } else {
            asm volatile("cp.async.wait_group 0;");
        }
        __syncthreads();
        const float* as = As[kt & 1];
        const float* bs = Bs[kt & 1];
#pragma unroll
        for (int k8 = 0; k8 < 2; k8++) {
            const int kb = k8 * 8;
            uint32_t a[4][4], bq[4][2];
#pragma unroll
            for (int mi = 0; mi < 4; mi++) {
                int rb = (wm * 64 + mi * 16 + r0) * AST + kb + kk * 2;
                float2 lo = *(const float2*)&as[rb];
                float2 hi = *(const float2*)&as[rb + 8 * AST];
                a[mi][0] = __float_as_uint(lo.x); a[mi][1] = __float_as_uint(hi.x);
                a[mi][2] = __float_as_uint(lo.y); a[mi][3] = __float_as_uint(hi.y);
            }
#pragma unroll
            for (int ni = 0; ni < 4; ni++) {
                int cb = wn * 32 + ni * 8 + r0;
                bq[ni][0] = __float_as_uint(bs[(kb + kk * 2) * BST + cb]);
                bq[ni][1] = __float_as_uint(bs[(kb + kk * 2 + 1) * BST + cb]);
            }
#pragma unroll
            for (int mi = 0; mi < 4; mi++)
#pragma unroll
                for (int ni = 0; ni < 4; ni++)
                    mma8(acc[mi][ni], a[mi], bq[ni]);
        }
        __syncthreads();
    }
    const int c2 = (lane & 3) * 2;
#pragma unroll
    for (int mi = 0; mi < 4; mi++) {
#pragma unroll
        for (int ni = 0; ni < 4; ni++) {
            int row = tm + wm * 64 + mi * 16 + r0;
            int col = tn + wn * 32 + ni * 8 + c2;
            if (MODE == 0) {
                *(float2*)&g_qkv[(size_t)row * N + col] =
                    make_float2(acc[mi][ni][0], acc[mi][ni][1]);
                *(float2*)&g_qkv[(size_t)(row + 8) * N + col] =
                    make_float2(acc[mi][ni][2], acc[mi][ni][3]);
            } else {
                float b0 = g_bias[col], b1 = g_bias[col + 1];
                *(float2*)&outp[scat_idx(row, col)] =
                    make_float2(acc[mi][ni][0] + b0, acc[mi][ni][1] + b1);
                *(float2*)&outp[scat_idx(row + 8, col)] =
                    make_float2(acc[mi][ni][2] + b0, acc[mi][ni][3] + b1);
            }
        }
    }
}

// ---- attention: one CTA per (window, head), 64 threads, f32x2 math ----
__global__ void __launch_bounds__(64) attn_k() {
    __shared__ float Ks[64 * 64];
    __shared__ float Vs[64 * 64];
    const int win = blockIdx.y, hd = blockIdx.x, t = threadIdx.x;
    const float* base = g_qkv + (size_t)win * 64 * QKVD;
#pragma unroll
    for (int i = 0; i < 16; i++) {
        int idx = i * 64 + t;
        int r = idx >> 4, v4 = idx & 15;
        *(float4*)&Ks[r * 64 + v4 * 4] =
            *(const float4*)&base[(size_t)r * QKVD + INNERD + hd * 64 + v4 * 4];
        *(float4*)&Vs[r * 64 + v4 * 4] =
            *(const float4*)&base[(size_t)r * QKVD + 2 * INNERD + hd * 64 + v4 * 4];
    }
    float s[64];
    {
        u64 qp[32];
        const float4* qrow = (const float4*)(base + (size_t)t * QKVD + hd * 64);
#pragma unroll
        for (int i = 0; i < 16; i++) {
            float4 v = qrow[i];
            qp[2 * i]     = pk2(v.x * 0.125f, v.y * 0.125f);
            qp[2 * i + 1] = pk2(v.z * 0.125f, v.w * 0.125f);
        }
        __syncthreads();
#pragma unroll 4
        for (int k = 0; k < 64; k++) {
            const ulonglong2* Kr = (const ulonglong2*)&Ks[k * 64];
            u64 a0 = 0, a1 = 0;
#pragma unroll
            for (int i = 0; i < 16; i++) {
                ulonglong2 kv = Kr[i];
                fma2(a0, qp[2 * i], kv.x);
                fma2(a1, qp[2 * i + 1], kv.y);
            }
            float x0, x1, y0, y1;
            upk2(a0, x0, x1); upk2(a1, y0, y1);
            s[k] = (x0 + x1) + (y0 + y1);
        }
    }
    float m = -1e30f;
#pragma unroll
    for (int k = 0; k < 64; k++) m = fmaxf(m, s[k]);
    float sum = 0.f;
#pragma unroll
    for (int k = 0; k < 64; k++) { s[k] = __expf(s[k] - m); sum += s[k]; }
    const float inv = 1.f / sum;
    u64 op[32];
#pragma unroll
    for (int i = 0; i < 32; i++) op[i] = 0;
#pragma unroll 4
    for (int k = 0; k < 64; k++) {
        float p = s[k] * inv;
        u64 pp = pk2(p, p);
        const ulonglong2* Vr = (const ulonglong2*)&Vs[k * 64];
#pragma unroll
        for (int i = 0; i < 16; i++) {
            ulonglong2 vv = Vr[i];
            fma2(op[2 * i], pp, vv.x);
            fma2(op[2 * i + 1], pp, vv.y);
        }
    }
    // store with pk8 interleave on the e = hd*64 + d dimension
    float* orow = g_o + ((size_t)win * 64 + t) * INNERD + hd * 64;
#pragma unroll
    for (int i = 0; i < 16; i++) {
        float f0, f1, f2, f3;
        upk2(op[2 * i], f0, f1); upk2(op[2 * i + 1], f2, f3);
        int bse = (i >> 1) * 8 + (i & 1);
        orow[bse]     = tf32r(f0);
        orow[bse + 2] = tf32r(f1);
        orow[bse + 4] = tf32r(f2);
        orow[bse + 6] = tf32r(f3);
    }
}

extern "C" void kernel_launch(void* const* d_in, const int* in_sizes, int n_in,
                              void* d_out, int out_size) {
    const float* x     = (const float*)d_in[0];
    const float* w_qkv = (const float*)d_in[1];
    const float* w_out = (const float*)d_in[2];
    const float* b_out = (const float*)d_in[3];
    float* out = (float*)d_out;

    perm_wqkv_k<<<1024, 384>>>(w_qkv);
    perm_wout_k<<<512, 1024>>>(w_out, b_out);
    gather_k<<<2048, 256>>>(x);
    gemm_tf32_k<TOKD, QKVD, 0><<<dim3(QKVD / 128, NTOK / 128), 256>>>(nullptr);
    attn_k<<<dim3(8, 512), 64>>>();
    gemm_tf32_k<INNERD, TOKD, 1><<<dim3(TOKD / 128, NTOK / 128), 256>>>(out);
}

// round 6
// speedup vs baseline: 1.2557x; 1.2557x over previous
#include <cuda_runtime.h>
#include <cuda_bf16.h>
#include <cstdint>
#include <cstddef>

#define DEV_INLINE __device__ __forceinline__
typedef unsigned long long u64;

// B=8, C=64, S=256, WS=32, P=4, HEADS=8, DH=64
constexpr int NTOK = 32768;      // 512 windows * 64 tokens
constexpr int TOKD = 1024;
constexpr int QKVD = 1536;
constexpr int INNERD = 512;

// ---- static scratch ----
__device__ float g_tokens[(size_t)NTOK * TOKD];
__device__ float g_qkv[(size_t)NTOK * QKVD];
__device__ float g_o[(size_t)NTOK * INNERD];
__device__ float g_wqkv[(size_t)TOKD * QKVD];
__device__ float g_wout[(size_t)INNERD * TOKD];
__device__ float g_bias[TOKD];

DEV_INLINE float tf32r(float v) {
    uint32_t u; asm("cvt.rna.tf32.f32 %0, %1;" : "=r"(u) : "f"(v));
    return __uint_as_float(u);
}
DEV_INLINE void mma8(float* d, const uint32_t* a, const uint32_t* b) {
    asm volatile("mma.sync.aligned.m16n8k8.row.col.f32.tf32.tf32.f32 "
        "{%0,%1,%2,%3}, {%4,%5,%6,%7}, {%8,%9}, {%0,%1,%2,%3};"
        : "+f"(d[0]), "+f"(d[1]), "+f"(d[2]), "+f"(d[3])
        : "r"(a[0]), "r"(a[1]), "r"(a[2]), "r"(a[3]), "r"(b[0]), "r"(b[1]));
}
DEV_INLINE void cp16(float* dst, const float* src) {
    uint32_t a = (uint32_t)__cvta_generic_to_shared(dst);
    asm volatile("cp.async.ca.shared.global [%0], [%1], 16;" :: "r"(a), "l"(src));
}
DEV_INLINE void fma2(u64& d, u64 a, u64 b) {
    asm("fma.rn.f32x2 %0, %1, %2, %0;" : "+l"(d) : "l"(a), "l"(b));
}
DEV_INLINE u64 pk2(float x, float y) {
    u64 r; asm("mov.b64 %0, {%1,%2};" : "=l"(r) : "r"(__float_as_uint(x)), "r"(__float_as_uint(y)));
    return r;
}
DEV_INLINE void upk2(u64 v, float& x, float& y) {
    uint32_t a, b; asm("mov.b64 {%0,%1}, %2;" : "=r"(a), "=r"(b) : "l"(v));
    x = __uint_as_float(a); y = __uint_as_float(b);
}

// ---- weight permutation: d' = c*16 + p1*4 + p2 ; orig d = (p1*4+p2)*64 + c ----
__global__ void perm_wqkv_k(const float* __restrict__ w) {
    int dp = blockIdx.x;                       // d' 0..1023
    int src = (dp & 15) * 64 + (dp >> 4);
    float4 v = ((const float4*)(w + (size_t)src * QKVD))[threadIdx.x];  // 384 thr
    v.x = tf32r(v.x); v.y = tf32r(v.y); v.z = tf32r(v.z); v.w = tf32r(v.w);
    ((float4*)(g_wqkv + (size_t)dp * QKVD))[threadIdx.x] = v;
}
__global__ void perm_wout_k(const float* __restrict__ w, const float* __restrict__ b) {
    int e = blockIdx.x;                        // 0..511
    int dp = threadIdx.x;                      // 0..1023
    int src = (dp & 15) * 64 + (dp >> 4);
    g_wout[(size_t)e * TOKD + dp] = tf32r(w[(size_t)e * TOKD + src]);
    if (e == 0) g_bias[dp] = b[src];
}

// ---- gather: x[b,c,h,w] -> tokens[win*64+t][d'] (tf32-rounded, float4) ----
__global__ void gather_k(const float* __restrict__ x) {
    int blk = blockIdx.x;                // 2048 = b*256 + h
    int b = blk >> 8, h = blk & 255;
    int tid = threadIdx.x;               // 256
    int w4 = tid & 63, c0 = tid >> 6;
    int h1 = h >> 5, hh = h & 31, nh_i = hh >> 2, p1 = hh & 3;
    int w1 = w4 >> 3, nw_j = w4 & 7;
    int win = b * 64 + h1 * 8 + w1;
    int t = nh_i * 8 + nw_j;
    size_t drow = ((size_t)win * 64 + t) * TOKD + p1 * 4;
    size_t sbase = (((size_t)b * 64) * 256 + h) * 256 + w4 * 4;
#pragma unroll
    for (int i = 0; i < 16; i++) {
        int c = c0 * 16 + i;
        float4 v = *(const float4*)&x[sbase + (size_t)c * 65536];
        v.x = tf32r(v.x); v.y = tf32r(v.y); v.z = tf32r(v.z); v.w = tf32r(v.w);
        *(float4*)&g_tokens[drow + (size_t)c * 16] = v;
    }
}

// scatter index for fused out-GEMM epilogue: (row=token, col=d') -> x layout
DEV_INLINE size_t scat_idx(int row, int col) {
    int win = row >> 6, t = row & 63;
    int b = win >> 6, rem = win & 63;
    int hh = ((rem >> 3) << 5) + ((t >> 3) << 2) + ((col >> 2) & 3);
    int ww = ((rem & 7) << 5) + ((t & 7) << 2) + (col & 3);
    int c = col >> 4;
    return ((((size_t)(b * 64 + c) << 8) + hh) << 8) + ww;
}

// ---- tf32 GEMM: 128x128 CTA tile, 4 warps (2x2) of 64x64, K-step 16 ----
// MODE 0: g_qkv = g_tokens @ g_wqkv                 (K=1024, N=1536)
// MODE 1: out[scattered] = g_o @ g_wout + bias      (K=512,  N=1024)
constexpr int AST = 20;    // A smem stride
constexpr int BST = 136;   // B smem stride
template<int K, int N, int MODE>
__global__ void __launch_bounds__(128, 2) gemm_tf32_k(float* __restrict__ outp) {
    __shared__ float As[2][128 * AST];
    __shared__ float Bs[2][16 * BST];
    const float* A = (MODE == 0) ? g_tokens : g_o;
    const float* B = (MODE == 0) ? g_wqkv : g_wout;

    const int tid = threadIdx.x, warp = tid >> 5, lane = tid & 31;
    const int wm = warp >> 1, wn = warp & 1;       // 2 x 2 warps, 64x64 tiles
    const int tm = blockIdx.y * 128, tn = blockIdx.x * 128;
    const int r0 = lane >> 2, kk = lane & 3;

    const int ar = tid >> 2, ak4 = tid & 3;        // A: rows ar+{0,32,64,96}
    const int br = tid >> 5, bn4 = tid & 31;       // B: rows br+{0,4,8,12}

    float acc[4][8][4];
#pragma unroll
    for (int mi = 0; mi < 4; mi++)
#pragma unroll
        for (int ni = 0; ni < 8; ni++)
#pragma unroll
            for (int j = 0; j < 4; j++) acc[mi][ni][j] = 0.f;

    constexpr int KT = K / 16;
#pragma unroll
    for (int i = 0; i < 4; i++)
        cp16(&As[0][(ar + i * 32) * AST + ak4 * 4],
             &A[(size_t)(tm + ar + i * 32) * K + ak4 * 4]);
#pragma unroll
    for (int i = 0; i < 4; i++)
        cp16(&Bs[0][(br + i * 4) * BST + bn4 * 4],
             &B[(size_t)(br + i * 4) * N + tn + bn4 * 4]);
    asm volatile("cp.async.commit_group;");

    for (int kt = 0; kt < KT; kt++) {
        if (kt + 1 < KT) {
            const int k0 = (kt + 1) * 16, bf = (kt + 1) & 1;
#pragma unroll
            for (int i = 0; i < 4; i++)
                cp16(&As[bf][(ar + i * 32) * AST + ak4 * 4],
                     &A[(size_t)(tm + ar + i * 32) * K + k0 + ak4 * 4]);
#pragma unroll
            for (int i = 0; i < 4; i++)
                cp16(&Bs[bf][(br + i * 4) * BST + bn4 * 4],
                     &B[(size_t)(k0 + br + i * 4) * N + tn + bn4 * 4]);
            asm volatile("cp.async.commit_group;");
            asm volatile("cp.async.wait_group 1;");
        } else {
            asm volatile("cp.async.wait_group 0;");
        }
        __syncthreads();
        const float* as = As[kt & 1];
        const float* bs = Bs[kt & 1];
#pragma unroll
        for (int k8 = 0; k8 < 2; k8++) {
            const int kb = k8 * 8;
            uint32_t a[4][4], bq[8][2];
#pragma unroll
            for (int mi = 0; mi < 4; mi++) {
                int rb = (wm * 64 + mi * 16 + r0) * AST + kb + kk;
                a[mi][0] = __float_as_uint(as[rb]);
                a[mi][1] = __float_as_uint(as[rb + 8 * AST]);
                a[mi][2] = __float_as_uint(as[rb + 4]);
                a[mi][3] = __float_as_uint(as[rb + 8 * AST + 4]);
            }
#pragma unroll
            for (int ni = 0; ni < 8; ni++) {
                int cb = wn * 64 + ni * 8 + r0;
                bq[ni][0] = __float_as_uint(bs[(kb + kk) * BST + cb]);
                bq[ni][1] = __float_as_uint(bs[(kb + kk + 4) * BST + cb]);
            }
#pragma unroll
            for (int mi = 0; mi < 4; mi++)
#pragma unroll
                for (int ni = 0; ni < 8; ni++)
                    mma8(acc[mi][ni], a[mi], bq[ni]);
        }
        __syncthreads();
    }
    const int c2 = (lane & 3) * 2;
#pragma unroll
    for (int mi = 0; mi < 4; mi++) {
#pragma unroll
        for (int ni = 0; ni < 8; ni++) {
            int row = tm + wm * 64 + mi * 16 + r0;
            int col = tn + wn * 64 + ni * 8 + c2;
            if (MODE == 0) {
                *(float2*)&g_qkv[(size_t)row * N + col] =
                    make_float2(acc[mi][ni][0], acc[mi][ni][1]);
                *(float2*)&g_qkv[(size_t)(row + 8) * N + col] =
                    make_float2(acc[mi][ni][2], acc[mi][ni][3]);
            } else {
                float b0 = g_bias[col], b1 = g_bias[col + 1];
                *(float2*)&outp[scat_idx(row, col)] =
                    make_float2(acc[mi][ni][0] + b0, acc[mi][ni][1] + b1);
                *(float2*)&outp[scat_idx(row + 8, col)] =
                    make_float2(acc[mi][ni][2] + b0, acc[mi][ni][3] + b1);
            }
        }
    }
}

// ---- attention: one CTA per (window, head), 64 threads, f32x2 math ----
__global__ void __launch_bounds__(64) attn_k() {
    __shared__ float Ks[64 * 64];
    __shared__ float Vs[64 * 64];
    const int win = blockIdx.y, hd = blockIdx.x, t = threadIdx.x;
    const float* base = g_qkv + (size_t)win * 64 * QKVD;
#pragma unroll
    for (int i = 0; i < 16; i++) {
        int idx = i * 64 + t;
        int r = idx >> 4, v4 = idx & 15;
        *(float4*)&Ks[r * 64 + v4 * 4] =
            *(const float4*)&base[(size_t)r * QKVD + INNERD + hd * 64 + v4 * 4];
        *(float4*)&Vs[r * 64 + v4 * 4] =
            *(const float4*)&base[(size_t)r * QKVD + 2 * INNERD + hd * 64 + v4 * 4];
    }
    float s[64];
    {
        u64 qp[32];
        const float4* qrow = (const float4*)(base + (size_t)t * QKVD + hd * 64);
#pragma unroll
        for (int i = 0; i < 16; i++) {
            float4 v = qrow[i];
            qp[2 * i]     = pk2(v.x * 0.125f, v.y * 0.125f);
            qp[2 * i + 1] = pk2(v.z * 0.125f, v.w * 0.125f);
        }
        __syncthreads();
#pragma unroll 4
        for (int k = 0; k < 64; k++) {
            const ulonglong2* Kr = (const ulonglong2*)&Ks[k * 64];
            u64 a0 = 0, a1 = 0;
#pragma unroll
            for (int i = 0; i < 16; i++) {
                ulonglong2 kv = Kr[i];
                fma2(a0, qp[2 * i], kv.x);
                fma2(a1, qp[2 * i + 1], kv.y);
            }
            float x0, x1, y0, y1;
            upk2(a0, x0, x1); upk2(a1, y0, y1);
            s[k] = (x0 + x1) + (y0 + y1);
        }
    }
    float m = -1e30f;
#pragma unroll
    for (int k = 0; k < 64; k++) m = fmaxf(m, s[k]);
    float sum = 0.f;
#pragma unroll
    for (int k = 0; k < 64; k++) { s[k] = __expf(s[k] - m); sum += s[k]; }
    const float inv = 1.f / sum;
    u64 op[32];
#pragma unroll
    for (int i = 0; i < 32; i++) op[i] = 0;
#pragma unroll 4
    for (int k = 0; k < 64; k++) {
        float p = s[k] * inv;
        u64 pp = pk2(p, p);
        const ulonglong2* Vr = (const ulonglong2*)&Vs[k * 64];
#pragma unroll
        for (int i = 0; i < 16; i++) {
            ulonglong2 vv = Vr[i];
            fma2(op[2 * i], pp, vv.x);
            fma2(op[2 * i + 1], pp, vv.y);
        }
    }
    float4* orow = (float4*)(g_o + ((size_t)win * 64 + t) * INNERD + hd * 64);
#pragma unroll
    for (int i = 0; i < 16; i++) {
        float f0, f1, f2, f3;
        upk2(op[2 * i], f0, f1); upk2(op[2 * i + 1], f2, f3);
        float4 v;
        v.x = tf32r(f0); v.y = tf32r(f1); v.z = tf32r(f2); v.w = tf32r(f3);
        orow[i] = v;
    }
}

extern "C" void kernel_launch(void* const* d_in, const int* in_sizes, int n_in,
                              void* d_out, int out_size) {
    const float* x     = (const float*)d_in[0];
    const float* w_qkv = (const float*)d_in[1];
    const float* w_out = (const float*)d_in[2];
    const float* b_out = (const float*)d_in[3];
    float* out = (float*)d_out;

    perm_wqkv_k<<<1024, 384>>>(w_qkv);
    perm_wout_k<<<512, 1024>>>(w_out, b_out);
    gather_k<<<2048, 256>>>(x);
    gemm_tf32_k<TOKD, QKVD, 0><<<dim3(QKVD / 128, NTOK / 128), 128>>>(nullptr);
    attn_k<<<dim3(8, 512), 64>>>();
    gemm_tf32_k<INNERD, TOKD, 1><<<dim3(TOKD / 128, NTOK / 128), 128>>>(out);
}

// round 8
// speedup vs baseline: 2.0420x; 1.6262x over previous
#include <cuda_runtime.h>
#include <cuda_fp16.h>
#include <cstdint>
#include <cstddef>

#define DEV_INLINE __device__ __forceinline__
typedef unsigned long long u64;

// B=8, C=64, S=256, WS=32, P=4, HEADS=8, DH=64
constexpr int NTOK = 32768;
constexpr int TOKD = 1024;
constexpr int QKVD = 1536;
constexpr int INNERD = 512;

// ---- static scratch ----
__device__ __half g_tokens[(size_t)NTOK * TOKD];          // [token][k]
__device__ __half g_qkv[(size_t)NTOK * QKVD];             // [token][f]
__device__ __half g_o[(size_t)NTOK * INNERD];             // [token][e]
__device__ uint32_t g_wqkv[(size_t)(TOKD / 2) * QKVD];    // k2-packed half2 [k2][n]
__device__ uint32_t g_wout[(size_t)(INNERD / 2) * TOKD];  // e2-packed half2 [e2][dp]
__device__ float g_bias[TOKD];

DEV_INLINE void mma16(float* d, const uint32_t* a, const uint32_t* b) {
    asm volatile("mma.sync.aligned.m16n8k16.row.col.f32.f16.f16.f32 "
        "{%0,%1,%2,%3}, {%4,%5,%6,%7}, {%8,%9}, {%0,%1,%2,%3};"
        : "+f"(d[0]), "+f"(d[1]), "+f"(d[2]), "+f"(d[3])
        : "r"(a[0]), "r"(a[1]), "r"(a[2]), "r"(a[3]), "r"(b[0]), "r"(b[1]));
}
DEV_INLINE void cp16(const void* dst, const void* src) {
    uint32_t a = (uint32_t)__cvta_generic_to_shared(dst);
    asm volatile("cp.async.ca.shared.global [%0], [%1], 16;" :: "r"(a), "l"(src));
}
DEV_INLINE void fma2(u64& d, u64 a, u64 b) {
    asm("fma.rn.f32x2 %0, %1, %2, %0;" : "+l"(d) : "l"(a), "l"(b));
}
DEV_INLINE u64 pk2(float x, float y) {
    u64 r; asm("mov.b64 %0, {%1,%2};" : "=l"(r) : "r"(__float_as_uint(x)), "r"(__float_as_uint(y)));
    return r;
}
DEV_INLINE void upk2(u64 v, float& x, float& y) {
    uint32_t a, b; asm("mov.b64 {%0,%1}, %2;" : "=r"(a), "=r"(b) : "l"(v));
    x = __uint_as_float(a); y = __uint_as_float(b);
}
DEV_INLINE uint32_t h2u(__half2 h) { return *(uint32_t*)&h; }

// ---- weight prep: d' = c*16 + p1*4 + p2 ; src d = (p1*4+p2)*64 + c ----
// g_wqkv[k2][n] = half2(w[src(2k2)][n], w[src(2k2+1)][n])
__global__ void perm_wqkv_k(const float* __restrict__ w) {
    int dp2 = blockIdx.x;                      // 0..511
    int d0 = 2 * dp2, d1 = 2 * dp2 + 1;
    int s0 = (d0 & 15) * 64 + (d0 >> 4);
    int s1 = (d1 & 15) * 64 + (d1 >> 4);
    int n4 = threadIdx.x;                      // 0..383
    float4 a = ((const float4*)(w + (size_t)s0 * QKVD))[n4];
    float4 b = ((const float4*)(w + (size_t)s1 * QKVD))[n4];
    uint4 o;
    o.x = h2u(__floats2half2_rn(a.x, b.x));
    o.y = h2u(__floats2half2_rn(a.y, b.y));
    o.z = h2u(__floats2half2_rn(a.z, b.z));
    o.w = h2u(__floats2half2_rn(a.w, b.w));
    ((uint4*)(g_wqkv + (size_t)dp2 * QKVD))[n4] = o;
}
// g_wout[e2][dp] = half2(w_out[2e2][src(dp)], w_out[2e2+1][src(dp)])
__global__ void perm_wout_k(const float* __restrict__ w, const float* __restrict__ b) {
    int e2 = blockIdx.x;                       // 0..255
    int dp = threadIdx.x;                      // 0..1023
    int src = (dp & 15) * 64 + (dp >> 4);
    float v0 = w[(size_t)(2 * e2) * TOKD + src];
    float v1 = w[(size_t)(2 * e2 + 1) * TOKD + src];
    g_wout[(size_t)e2 * TOKD + dp] = h2u(__floats2half2_rn(v0, v1));
    if (e2 == 0) g_bias[dp] = b[src];
}

// ---- gather: x[b,c,h,w] -> g_tokens[win*64+t][d'] (fp16) ----
__global__ void gather_k(const float* __restrict__ x) {
    int blk = blockIdx.x;                // b*256 + h
    int b = blk >> 8, h = blk & 255;
    int tid = threadIdx.x;               // 256
    int w4 = tid & 63, c0 = tid >> 6;
    int h1 = h >> 5, hh = h & 31, nh_i = hh >> 2, p1 = hh & 3;
    int w1 = w4 >> 3, nw_j = w4 & 7;
    int win = b * 64 + h1 * 8 + w1;
    int t = nh_i * 8 + nw_j;
    size_t drow = ((size_t)win * 64 + t) * TOKD + p1 * 4;
    size_t sbase = (((size_t)b * 64) * 256 + h) * 256 + w4 * 4;
#pragma unroll
    for (int i = 0; i < 16; i++) {
        int c = c0 * 16 + i;
        float4 v = *(const float4*)&x[sbase + (size_t)c * 65536];
        uint2 o;
        o.x = h2u(__floats2half2_rn(v.x, v.y));
        o.y = h2u(__floats2half2_rn(v.z, v.w));
        *(uint2*)&g_tokens[drow + (size_t)c * 16] = o;
    }
}

// ---- fp16 GEMM: 128x128 CTA, 2x2 warps of 64x64, K-step 32, double-buffered ----
// MODE 0: g_qkv[t][f](fp16) = tokens @ wqkv      (K=1024, N=1536)
// MODE 1: out[scat(t,dp)] = g_o @ wout + bias    (K=512,  N=1024)
constexpr int AST = 40;    // A smem stride (halfs): 32 + 8
constexpr int BST = 136;   // B smem stride (u32):   128 + 8
template<int K, int N, int MODE>
__global__ void __launch_bounds__(128, 2) gemm_fp16_k(float* __restrict__ outp) {
    __shared__ __half As[2][128 * AST];
    __shared__ uint32_t Bs[2][16 * BST];
    const __half* A = (MODE == 0) ? g_tokens : g_o;
    const uint32_t* Bp = (MODE == 0) ? g_wqkv : g_wout;

    const int tid = threadIdx.x, warp = tid >> 5, lane = tid & 31;
    const int wm = warp >> 1, wn = warp & 1;
    const int tm = blockIdx.y * 128, tn = blockIdx.x * 128;
    const int r0 = lane >> 2, kk = lane & 3;

    float acc[4][8][4];
#pragma unroll
    for (int mi = 0; mi < 4; mi++)
#pragma unroll
        for (int ni = 0; ni < 8; ni++)
#pragma unroll
            for (int j = 0; j < 4; j++) acc[mi][ni][j] = 0.f;

    constexpr int KT = K / 32;
    constexpr int KH = K / 2;      // u32 rows of B

    auto load_stage = [&](int kt, int bf) {
        const int k0 = kt * 32;
#pragma unroll
        for (int i = 0; i < 4; i++) {
            int idx = i * 128 + tid;
            int r = idx >> 2, ch = idx & 3;
            cp16(&As[bf][r * AST + ch * 8], &A[(size_t)(tm + r) * K + k0 + ch * 8]);
        }
        const int k20 = k0 / 2;
#pragma unroll
        for (int i = 0; i < 4; i++) {
            int idx = i * 128 + tid;
            int kr = idx >> 5, n4 = idx & 31;
            cp16(&Bs[bf][kr * BST + n4 * 4], &Bp[(size_t)(k20 + kr) * N + tn + n4 * 4]);
        }
        asm volatile("cp.async.commit_group;");
    };

    load_stage(0, 0);

    for (int kt = 0; kt < KT; kt++) {
        if (kt + 1 < KT) {
            load_stage(kt + 1, (kt + 1) & 1);
            asm volatile("cp.async.wait_group 1;");
        } else {
            asm volatile("cp.async.wait_group 0;");
        }
        __syncthreads();
        const __half* as = As[kt & 1];
        const uint32_t* bs = Bs[kt & 1];
#pragma unroll
        for (int ks = 0; ks < 2; ks++) {
            uint32_t a[4][4], bq[8][2];
#pragma unroll
            for (int mi = 0; mi < 4; mi++) {
                int base = (wm * 64 + mi * 16 + r0) * AST + kk * 2 + ks * 16;
                a[mi][0] = *(const uint32_t*)&as[base];
                a[mi][1] = *(const uint32_t*)&as[base + 8 * AST];
                a[mi][2] = *(const uint32_t*)&as[base + 8];
                a[mi][3] = *(const uint32_t*)&as[base + 8 * AST + 8];
            }
#pragma unroll
            for (int ni = 0; ni < 8; ni++) {
                int cb = wn * 64 + ni * 8 + r0;
                bq[ni][0] = bs[(kk + 8 * ks) * BST + cb];
                bq[ni][1] = bs[(kk + 4 + 8 * ks) * BST + cb];
            }
#pragma unroll
            for (int mi = 0; mi < 4; mi++)
#pragma unroll
                for (int ni = 0; ni < 8; ni++)
                    mma16(acc[mi][ni], a[mi], bq[ni]);
        }
        __syncthreads();
    }
    const int c2 = (lane & 3) * 2;
#pragma unroll
    for (int mi = 0; mi < 4; mi++) {
#pragma unroll
        for (int ni = 0; ni < 8; ni++) {
            int row = tm + wm * 64 + mi * 16 + r0;
            int col = tn + wn * 64 + ni * 8 + c2;
            if (MODE == 0) {
                *(uint32_t*)&g_qkv[(size_t)row * N + col] =
                    h2u(__floats2half2_rn(acc[mi][ni][0], acc[mi][ni][1]));
                *(uint32_t*)&g_qkv[(size_t)(row + 8) * N + col] =
                    h2u(__floats2half2_rn(acc[mi][ni][2], acc[mi][ni][3]));
            } else {
                // scatter to x layout: row=token, col=d'
                int win = row >> 6, t = row & 63;
                int b = win >> 6, rem = win & 63;
                size_t xr = ((size_t)(b * 64) << 16)
                          + ((size_t)(((rem >> 3) << 5) | ((t >> 3) << 2) | ((col >> 2) & 3)) << 8)
                          + (size_t)(((rem & 7) << 5) | ((t & 7) << 2) | (col & 3));
                size_t cterm = (size_t)(col >> 4) << 16;
                float b0 = g_bias[col], b1 = g_bias[col + 1];
                *(float2*)&outp[xr + cterm] =
                    make_float2(acc[mi][ni][0] + b0, acc[mi][ni][1] + b1);
                // row+8: only t changes (t < 64 guaranteed within window)
                int t8 = t + 8;
                size_t xr8 = ((size_t)(b * 64) << 16)
                           + ((size_t)(((rem >> 3) << 5) | ((t8 >> 3) << 2) | ((col >> 2) & 3)) << 8)
                           + (size_t)(((rem & 7) << 5) | ((t8 & 7) << 2) | (col & 3));
                *(float2*)&outp[xr8 + cterm] =
                    make_float2(acc[mi][ni][2] + b0, acc[mi][ni][3] + b1);
            }
        }
    }
}

// ---- attention: one CTA per (window, head), 64 threads, f32x2 math, fp16 I/O ----
__global__ void __launch_bounds__(64) attn_k() {
    __shared__ float Ks[64 * 64];
    __shared__ float Vs[64 * 64];
    const int win = blockIdx.y, hd = blockIdx.x, t = threadIdx.x;
    const __half* base = g_qkv + (size_t)win * 64 * QKVD;
    // K/V: 64 rows x 64 halfs; load uint4 (8 halfs), convert to float smem
#pragma unroll
    for (int i = 0; i < 8; i++) {
        int idx = i * 64 + t;
        int r = idx >> 3, c8 = idx & 7;
        uint4 kv = *(const uint4*)&base[(size_t)r * QKVD + INNERD + hd * 64 + c8 * 8];
        uint4 vv = *(const uint4*)&base[(size_t)r * QKVD + 2 * INNERD + hd * 64 + c8 * 8];
        float* kd = &Ks[r * 64 + c8 * 8];
        float* vd = &Vs[r * 64 + c8 * 8];
        float2 f;
        f = __half22float2(*(__half2*)&kv.x); kd[0] = f.x; kd[1] = f.y;
        f = __half22float2(*(__half2*)&kv.y); kd[2] = f.x; kd[3] = f.y;
        f = __half22float2(*(__half2*)&kv.z); kd[4] = f.x; kd[5] = f.y;
        f = __half22float2(*(__half2*)&kv.w); kd[6] = f.x; kd[7] = f.y;
        f = __half22float2(*(__half2*)&vv.x); vd[0] = f.x; vd[1] = f.y;
        f = __half22float2(*(__half2*)&vv.y); vd[2] = f.x; vd[3] = f.y;
        f = __half22float2(*(__half2*)&vv.z); vd[4] = f.x; vd[5] = f.y;
        f = __half22float2(*(__half2*)&vv.w); vd[6] = f.x; vd[7] = f.y;
    }
    float s[64];
    {
        u64 qp[32];
        const uint4* qrow = (const uint4*)(base + (size_t)t * QKVD + hd * 64);
#pragma unroll
        for (int i = 0; i < 8; i++) {
            uint4 qv = qrow[i];
            float2 f0 = __half22float2(*(__half2*)&qv.x);
            float2 f1 = __half22float2(*(__half2*)&qv.y);
            float2 f2 = __half22float2(*(__half2*)&qv.z);
            float2 f3 = __half22float2(*(__half2*)&qv.w);
            qp[4 * i]     = pk2(f0.x * 0.125f, f0.y * 0.125f);
            qp[4 * i + 1] = pk2(f1.x * 0.125f, f1.y * 0.125f);
            qp[4 * i + 2] = pk2(f2.x * 0.125f, f2.y * 0.125f);
            qp[4 * i + 3] = pk2(f3.x * 0.125f, f3.y * 0.125f);
        }
        __syncthreads();
#pragma unroll 4
        for (int k = 0; k < 64; k++) {
            const ulonglong2* Kr = (const ulonglong2*)&Ks[k * 64];
            u64 a0 = 0, a1 = 0;
#pragma unroll
            for (int i = 0; i < 16; i++) {
                ulonglong2 kv = Kr[i];
                fma2(a0, qp[2 * i], kv.x);
                fma2(a1, qp[2 * i + 1], kv.y);
            }
            float x0, x1, y0, y1;
            upk2(a0, x0, x1); upk2(a1, y0, y1);
            s[k] = (x0 + x1) + (y0 + y1);
        }
    }
    float m = -1e30f;
#pragma unroll
    for (int k = 0; k < 64; k++) m = fmaxf(m, s[k]);
    float sum = 0.f;
#pragma unroll
    for (int k = 0; k < 64; k++) { s[k] = __expf(s[k] - m); sum += s[k]; }
    const float inv = 1.f / sum;
    u64 op[32];
#pragma unroll
    for (int i = 0; i < 32; i++) op[i] = 0;
#pragma unroll 4
    for (int k = 0; k < 64; k++) {
        float p = s[k] * inv;
        u64 pp = pk2(p, p);
        const ulonglong2* Vr = (const ulonglong2*)&Vs[k * 64];
#pragma unroll
        for (int i = 0; i < 16; i++) {
            ulonglong2 vv = Vr[i];
            fma2(op[2 * i], pp, vv.x);
            fma2(op[2 * i + 1], pp, vv.y);
        }
    }
    // store fp16
    uint4* orow = (uint4*)(g_o + ((size_t)win * 64 + t) * INNERD + hd * 64);
#pragma unroll
    for (int i = 0; i < 8; i++) {
        float f0, f1, f2, f3, f4, f5, f6, f7;
        upk2(op[4 * i], f0, f1);     upk2(op[4 * i + 1], f2, f3);
        upk2(op[4 * i + 2], f4, f5); upk2(op[4 * i + 3], f6, f7);
        uint4 o;
        o.x = h2u(__floats2half2_rn(f0, f1));
        o.y = h2u(__floats2half2_rn(f2, f3));
        o.z = h2u(__floats2half2_rn(f4, f5));
        o.w = h2u(__floats2half2_rn(f6, f7));
        orow[i] = o;
    }
}

extern "C" void kernel_launch(void* const* d_in, const int* in_sizes, int n_in,
                              void* d_out, int out_size) {
    const float* x     = (const float*)d_in[0];
    const float* w_qkv = (const float*)d_in[1];
    const float* w_out = (const float*)d_in[2];
    const float* b_out = (const float*)d_in[3];
    float* out = (float*)d_out;

    perm_wqkv_k<<<512, 384>>>(w_qkv);
    perm_wout_k<<<256, 1024>>>(w_out, b_out);
    gather_k<<<2048, 256>>>(x);
    gemm_fp16_k<TOKD, QKVD, 0><<<dim3(QKVD / 128, NTOK / 128), 128>>>(nullptr);
    attn_k<<<dim3(8, 512), 64>>>();
    gemm_fp16_k<INNERD, TOKD, 1><<<dim3(TOKD / 128, NTOK / 128), 128>>>(out);
}

// round 9
// speedup vs baseline: 2.2293x; 1.0917x over previous
#include <cuda_runtime.h>
#include <cuda_fp16.h>
#include <cstdint>
#include <cstddef>

#define DEV_INLINE __device__ __forceinline__
typedef unsigned long long u64;

// B=8, C=64, S=256, WS=32, P=4, HEADS=8, DH=64
constexpr int NTOK = 32768;
constexpr int TOKD = 1024;
constexpr int QKVD = 1536;
constexpr int INNERD = 512;

// ---- static scratch ----
__device__ __half g_tokens[(size_t)NTOK * TOKD];            // [token][k]
__device__ __half g_qkv[(size_t)NTOK * QKVD];               // [token][f]
__device__ __half g_o[(size_t)NTOK * INNERD];               // [token][e]
__device__ uint32_t g_wqkv[(size_t)QKVD * (TOKD / 2)];      // [f][k2]  half2-packed
__device__ uint32_t g_wout[(size_t)TOKD * (INNERD / 2)];    // [dp][e2] half2-packed
__device__ float g_bias[TOKD];

DEV_INLINE void mma16(float* d, const uint32_t* a, const uint32_t* b) {
    asm volatile("mma.sync.aligned.m16n8k16.row.col.f32.f16.f16.f32 "
        "{%0,%1,%2,%3}, {%4,%5,%6,%7}, {%8,%9}, {%0,%1,%2,%3};"
        : "+f"(d[0]), "+f"(d[1]), "+f"(d[2]), "+f"(d[3])
        : "r"(a[0]), "r"(a[1]), "r"(a[2]), "r"(a[3]), "r"(b[0]), "r"(b[1]));
}
DEV_INLINE void cp16(const void* dst, const void* src) {
    uint32_t a = (uint32_t)__cvta_generic_to_shared(dst);
    asm volatile("cp.async.ca.shared.global [%0], [%1], 16;" :: "r"(a), "l"(src));
}
DEV_INLINE void ldsm4(uint32_t* r, uint32_t addr) {
    asm volatile("ldmatrix.sync.aligned.m8n8.x4.shared.b16 {%0,%1,%2,%3}, [%4];"
        : "=r"(r[0]), "=r"(r[1]), "=r"(r[2]), "=r"(r[3]) : "r"(addr));
}
DEV_INLINE void fma2(u64& d, u64 a, u64 b) {
    asm("fma.rn.f32x2 %0, %1, %2, %0;" : "+l"(d) : "l"(a), "l"(b));
}
DEV_INLINE u64 pk2(float x, float y) {
    u64 r; asm("mov.b64 %0, {%1,%2};" : "=l"(r) : "r"(__float_as_uint(x)), "r"(__float_as_uint(y)));
    return r;
}
DEV_INLINE void upk2(u64 v, float& x, float& y) {
    uint32_t a, b; asm("mov.b64 {%0,%1}, %2;" : "=r"(a), "=r"(b) : "l"(v));
    x = __uint_as_float(a); y = __uint_as_float(b);
}
DEV_INLINE uint32_t h2u(__half2 h) { return *(uint32_t*)&h; }

// ---- weight prep: d' = c*16 + p1*4 + p2 ; src d = (p1*4+p2)*64 + c ----
// g_wqkv[f][k2] = half2(w[src(2k2)][f], w[src(2k2+1)][f]) via smem transpose
__global__ void perm_wqkv_k(const float* __restrict__ w) {
    __shared__ uint32_t sm[32][33];
    int k20 = blockIdx.x * 32, f0 = blockIdx.y * 32;
    int tx = threadIdx.x, ty = threadIdx.y;     // (32, 8)
#pragma unroll
    for (int i = 0; i < 4; i++) {
        int k2l = ty + i * 8;
        int d0 = 2 * (k20 + k2l), d1 = d0 + 1;
        int s0 = (d0 & 15) * 64 + (d0 >> 4);
        int s1 = (d1 & 15) * 64 + (d1 >> 4);
        sm[k2l][tx] = h2u(__floats2half2_rn(w[(size_t)s0 * QKVD + f0 + tx],
                                            w[(size_t)s1 * QKVD + f0 + tx]));
    }
    __syncthreads();
#pragma unroll
    for (int i = 0; i < 4; i++) {
        int fl = ty + i * 8;
        g_wqkv[(size_t)(f0 + fl) * (TOKD / 2) + k20 + tx] = sm[tx][fl];
    }
}
// g_wout[dp][e2] = half2(w_out[2e2][src(dp)], w_out[2e2+1][src(dp)])
// read over raw d (coalesced), map dp(d) = (d&63)*16 + (d>>6)
__global__ void perm_wout_k(const float* __restrict__ w, const float* __restrict__ b) {
    __shared__ uint32_t sm[32][33];
    int e20 = blockIdx.x * 32, d0 = blockIdx.y * 32;
    int tx = threadIdx.x, ty = threadIdx.y;     // (32, 8)
#pragma unroll
    for (int i = 0; i < 4; i++) {
        int e2l = ty + i * 8;
        int e = 2 * (e20 + e2l);
        sm[e2l][tx] = h2u(__floats2half2_rn(w[(size_t)e * TOKD + d0 + tx],
                                            w[(size_t)(e + 1) * TOKD + d0 + tx]));
    }
    __syncthreads();
#pragma unroll
    for (int i = 0; i < 4; i++) {
        int dl = ty + i * 8;
        int d = d0 + dl;
        int dp = (d & 63) * 16 + (d >> 6);
        g_wout[(size_t)dp * (INNERD / 2) + e20 + tx] = sm[tx][dl];
    }
    if (blockIdx.x == 0 && ty == 0) {
        int d = d0 + tx;
        g_bias[(d & 63) * 16 + (d >> 6)] = b[d];
    }
}

// ---- gather: x[b,c,h,w] -> g_tokens[win*64+t][d'] (fp16) ----
__global__ void gather_k(const float* __restrict__ x) {
    int blk = blockIdx.x;                // b*256 + h
    int b = blk >> 8, h = blk & 255;
    int tid = threadIdx.x;               // 256
    int w4 = tid & 63, c0 = tid >> 6;
    int h1 = h >> 5, hh = h & 31, nh_i = hh >> 2, p1 = hh & 3;
    int w1 = w4 >> 3, nw_j = w4 & 7;
    int win = b * 64 + h1 * 8 + w1;
    int t = nh_i * 8 + nw_j;
    size_t drow = ((size_t)win * 64 + t) * TOKD + p1 * 4;
    size_t sbase = (((size_t)b * 64) * 256 + h) * 256 + w4 * 4;
#pragma unroll
    for (int i = 0; i < 16; i++) {
        int c = c0 * 16 + i;
        float4 v = *(const float4*)&x[sbase + (size_t)c * 65536];
        uint2 o;
        o.x = h2u(__floats2half2_rn(v.x, v.y));
        o.y = h2u(__floats2half2_rn(v.z, v.w));
        *(uint2*)&g_tokens[drow + (size_t)c * 16] = o;
    }
}

// ---- fp16 GEMM: 128x128 CTA, 2x2 warps of 64x64, K-step 64, ldmatrix ----
// dynamic smem: A [2][128*72] half (36864B) | B [2][128*36] u32 (36864B)
constexpr int GEMM_SMEM = 73728;
template<int K, int N, int MODE>
__global__ void __launch_bounds__(128, 2) gemm_fp16_k(float* __restrict__ outp) {
    extern __shared__ char smem_raw[];
    __half* Asm = (__half*)smem_raw;
    uint32_t* Bsm = (uint32_t*)(smem_raw + 36864);
    const uint32_t sb = (uint32_t)__cvta_generic_to_shared(smem_raw);

    const __half* A = (MODE == 0) ? g_tokens : g_o;
    const uint32_t* Bp = (MODE == 0) ? g_wqkv : g_wout;
    constexpr int K2 = K / 2;

    const int tid = threadIdx.x, warp = tid >> 5, lane = tid & 31;
    const int wm = warp >> 1, wn = warp & 1;
    const int tm = blockIdx.y * 128, tn = blockIdx.x * 128;
    const int r0 = lane >> 2;

    float acc[4][8][4];
#pragma unroll
    for (int mi = 0; mi < 4; mi++)
#pragma unroll
        for (int ni = 0; ni < 8; ni++)
#pragma unroll
            for (int j = 0; j < 4; j++) acc[mi][ni][j] = 0.f;

    constexpr int KT = K / 64;
    const int lr = tid >> 3, lc = tid & 7;   // load row/chunk

    auto load_stage = [&](int kt, int bf) {
        const int k0 = kt * 64, k20 = kt * 32;
#pragma unroll
        for (int i = 0; i < 8; i++) {
            int r = lr + i * 16;
            cp16(&Asm[bf * 9216 + r * 72 + lc * 8], &A[(size_t)(tm + r) * K + k0 + lc * 8]);
        }
#pragma unroll
        for (int i = 0; i < 8; i++) {
            int r = lr + i * 16;
            cp16(&Bsm[bf * 4608 + r * 36 + lc * 4], &Bp[(size_t)(tn + r) * K2 + k20 + lc * 4]);
        }
        asm volatile("cp.async.commit_group;");
    };

    load_stage(0, 0);

    // per-lane ldmatrix base offsets
    const uint32_t a_lane = ((wm * 64 + (lane & 15)) * 72 + (lane >> 4) * 8) * 2;
    const uint32_t b_lane = ((wn * 64 + (lane >> 4) * 8 + (lane & 7)) * 36
                             + ((lane >> 3) & 1) * 4) * 4;

    for (int kt = 0; kt < KT; kt++) {
        if (kt + 1 < KT) {
            load_stage(kt + 1, (kt + 1) & 1);
            asm volatile("cp.async.wait_group 1;");
        } else {
            asm volatile("cp.async.wait_group 0;");
        }
        __syncthreads();
        const uint32_t abuf = sb + (kt & 1) * 18432 + a_lane;
        const uint32_t bbuf = sb + 36864 + (kt & 1) * 18432 + b_lane;
#pragma unroll
        for (int ks = 0; ks < 4; ks++) {
            uint32_t a[4][4], bq[8][2];
#pragma unroll
            for (int mi = 0; mi < 4; mi++)
                ldsm4(a[mi], abuf + mi * 2304 + ks * 32);
#pragma unroll
            for (int p = 0; p < 4; p++) {
                uint32_t t4[4];
                ldsm4(t4, bbuf + p * 2304 + ks * 32);
                bq[2 * p][0] = t4[0]; bq[2 * p][1] = t4[1];
                bq[2 * p + 1][0] = t4[2]; bq[2 * p + 1][1] = t4[3];
            }
#pragma unroll
            for (int mi = 0; mi < 4; mi++)
#pragma unroll
                for (int ni = 0; ni < 8; ni++)
                    mma16(acc[mi][ni], a[mi], bq[ni]);
        }
        __syncthreads();
    }
    const int c2 = (lane & 3) * 2;
#pragma unroll
    for (int mi = 0; mi < 4; mi++) {
#pragma unroll
        for (int ni = 0; ni < 8; ni++) {
            int row = tm + wm * 64 + mi * 16 + r0;
            int col = tn + wn * 64 + ni * 8 + c2;
            if (MODE == 0) {
                *(uint32_t*)&g_qkv[(size_t)row * N + col] =
                    h2u(__floats2half2_rn(acc[mi][ni][0], acc[mi][ni][1]));
                *(uint32_t*)&g_qkv[(size_t)(row + 8) * N + col] =
                    h2u(__floats2half2_rn(acc[mi][ni][2], acc[mi][ni][3]));
            } else {
                int win = row >> 6, t = row & 63;
                int b = win >> 6, rem = win & 63;
                size_t cterm = (size_t)(col >> 4) << 16;
                float b0 = g_bias[col], b1 = g_bias[col + 1];
                size_t xr = ((size_t)(b * 64) << 16)
                          + ((size_t)(((rem >> 3) << 5) | ((t >> 3) << 2) | ((col >> 2) & 3)) << 8)
                          + (size_t)(((rem & 7) << 5) | ((t & 7) << 2) | (col & 3));
                *(float2*)&outp[xr + cterm] =
                    make_float2(acc[mi][ni][0] + b0, acc[mi][ni][1] + b1);
                int t8 = t + 8;
                size_t xr8 = ((size_t)(b * 64) << 16)
                           + ((size_t)(((rem >> 3) << 5) | ((t8 >> 3) << 2) | ((col >> 2) & 3)) << 8)
                           + (size_t)(((rem & 7) << 5) | ((t8 & 7) << 2) | (col & 3));
                *(float2*)&outp[xr8 + cterm] =
                    make_float2(acc[mi][ni][2] + b0, acc[mi][ni][3] + b1);
            }
        }
    }
}

// ---- attention: one CTA per (window, head), 64 threads, f32x2 math, fp16 I/O ----
__global__ void __launch_bounds__(64) attn_k() {
    __shared__ float Ks[64 * 64];
    __shared__ float Vs[64 * 64];
    const int win = blockIdx.y, hd = blockIdx.x, t = threadIdx.x;
    const __half* base = g_qkv + (size_t)win * 64 * QKVD;
#pragma unroll
    for (int i = 0; i < 8; i++) {
        int idx = i * 64 + t;
        int r = idx >> 3, c8 = idx & 7;
        uint4 kv = *(const uint4*)&base[(size_t)r * QKVD + INNERD + hd * 64 + c8 * 8];
        uint4 vv = *(const uint4*)&base[(size_t)r * QKVD + 2 * INNERD + hd * 64 + c8 * 8];
        float* kd = &Ks[r * 64 + c8 * 8];
        float* vd = &Vs[r * 64 + c8 * 8];
        float2 f;
        f = __half22float2(*(__half2*)&kv.x); kd[0] = f.x; kd[1] = f.y;
        f = __half22float2(*(__half2*)&kv.y); kd[2] = f.x; kd[3] = f.y;
        f = __half22float2(*(__half2*)&kv.z); kd[4] = f.x; kd[5] = f.y;
        f = __half22float2(*(__half2*)&kv.w); kd[6] = f.x; kd[7] = f.y;
        f = __half22float2(*(__half2*)&vv.x); vd[0] = f.x; vd[1] = f.y;
        f = __half22float2(*(__half2*)&vv.y); vd[2] = f.x; vd[3] = f.y;
        f = __half22float2(*(__half2*)&vv.z); vd[4] = f.x; vd[5] = f.y;
        f = __half22float2(*(__half2*)&vv.w); vd[6] = f.x; vd[7] = f.y;
    }
    float s[64];
    {
        u64 qp[32];
        const uint4* qrow = (const uint4*)(base + (size_t)t * QKVD + hd * 64);
#pragma unroll
        for (int i = 0; i < 8; i++) {
            uint4 qv = qrow[i];
            float2 f0 = __half22float2(*(__half2*)&qv.x);
            float2 f1 = __half22float2(*(__half2*)&qv.y);
            float2 f2 = __half22float2(*(__half2*)&qv.z);
            float2 f3 = __half22float2(*(__half2*)&qv.w);
            qp[4 * i]     = pk2(f0.x * 0.125f, f0.y * 0.125f);
            qp[4 * i + 1] = pk2(f1.x * 0.125f, f1.y * 0.125f);
            qp[4 * i + 2] = pk2(f2.x * 0.125f, f2.y * 0.125f);
            qp[4 * i + 3] = pk2(f3.x * 0.125f, f3.y * 0.125f);
        }
        __syncthreads();
#pragma unroll 4
        for (int k = 0; k < 64; k++) {
            const ulonglong2* Kr = (const ulonglong2*)&Ks[k * 64];
            u64 a0 = 0, a1 = 0;
#pragma unroll
            for (int i = 0; i < 16; i++) {
                ulonglong2 kv = Kr[i];
                fma2(a0, qp[2 * i], kv.x);
                fma2(a1, qp[2 * i + 1], kv.y);
            }
            float x0, x1, y0, y1;
            upk2(a0, x0, x1); upk2(a1, y0, y1);
            s[k] = (x0 + x1) + (y0 + y1);
        }
    }
    float m = -1e30f;
#pragma unroll
    for (int k = 0; k < 64; k++) m = fmaxf(m, s[k]);
    float sum = 0.f;
#pragma unroll
    for (int k = 0; k < 64; k++) { s[k] = __expf(s[k] - m); sum += s[k]; }
    const float inv = 1.f / sum;
    u64 op[32];
#pragma unroll
    for (int i = 0; i < 32; i++) op[i] = 0;
#pragma unroll 4
    for (int k = 0; k < 64; k++) {
        float p = s[k] * inv;
        u64 pp = pk2(p, p);
        const ulonglong2* Vr = (const ulonglong2*)&Vs[k * 64];
#pragma unroll
        for (int i = 0; i < 16; i++) {
            ulonglong2 vv = Vr[i];
            fma2(op[2 * i], pp, vv.x);
            fma2(op[2 * i + 1], pp, vv.y);
        }
    }
    uint4* orow = (uint4*)(g_o + ((size_t)win * 64 + t) * INNERD + hd * 64);
#pragma unroll
    for (int i = 0; i < 8; i++) {
        float f0, f1, f2, f3, f4, f5, f6, f7;
        upk2(op[4 * i], f0, f1);     upk2(op[4 * i + 1], f2, f3);
        upk2(op[4 * i + 2], f4, f5); upk2(op[4 * i + 3], f6, f7);
        uint4 o;
        o.x = h2u(__floats2half2_rn(f0, f1));
        o.y = h2u(__floats2half2_rn(f2, f3));
        o.z = h2u(__floats2half2_rn(f4, f5));
        o.w = h2u(__floats2half2_rn(f6, f7));
        orow[i] = o;
    }
}

extern "C" void kernel_launch(void* const* d_in, const int* in_sizes, int n_in,
                              void* d_out, int out_size) {
    const float* x     = (const float*)d_in[0];
    const float* w_qkv = (const float*)d_in[1];
    const float* w_out = (const float*)d_in[2];
    const float* b_out = (const float*)d_in[3];
    float* out = (float*)d_out;

    cudaFuncSetAttribute(gemm_fp16_k<TOKD, QKVD, 0>,
                         cudaFuncAttributeMaxDynamicSharedMemorySize, GEMM_SMEM);
    cudaFuncSetAttribute(gemm_fp16_k<INNERD, TOKD, 1>,
                         cudaFuncAttributeMaxDynamicSharedMemorySize, GEMM_SMEM);

    perm_wqkv_k<<<dim3(TOKD / 64, QKVD / 32), dim3(32, 8)>>>(w_qkv);
    perm_wout_k<<<dim3(INNERD / 64, TOKD / 32), dim3(32, 8)>>>(w_out, b_out);
    gather_k<<<2048, 256>>>(x);
    gemm_fp16_k<TOKD, QKVD, 0>
        <<<dim3(QKVD / 128, NTOK / 128), 128, GEMM_SMEM>>>(nullptr);
    attn_k<<<dim3(8, 512), 64>>>();
    gemm_fp16_k<INNERD, TOKD, 1>
        <<<dim3(TOKD / 128, NTOK / 128), 128, GEMM_SMEM>>>(out);
}

// round 10
// speedup vs baseline: 2.5931x; 1.1632x over previous
#include <cuda_runtime.h>
#include <cuda_fp16.h>
#include <cstdint>
#include <cstddef>

#define DEV_INLINE __device__ __forceinline__

// B=8, C=64, S=256, WS=32, P=4, HEADS=8, DH=64
constexpr int NTOK = 32768;
constexpr int TOKD = 1024;
constexpr int QKVD = 1536;
constexpr int INNERD = 512;

// ---- static scratch ----
__device__ __half g_tokens[(size_t)NTOK * TOKD];            // [token][k]
__device__ __half g_qkv[(size_t)NTOK * QKVD];               // [token][f]
__device__ __half g_o[(size_t)NTOK * INNERD];               // [token][e]
__device__ uint32_t g_wqkv[(size_t)QKVD * (TOKD / 2)];      // [f][k2]  half2-packed
__device__ uint32_t g_wout[(size_t)TOKD * (INNERD / 2)];    // [dp][e2] half2-packed
__device__ float g_bias[TOKD];

DEV_INLINE void mma16(float* d, const uint32_t* a, const uint32_t* b) {
    asm volatile("mma.sync.aligned.m16n8k16.row.col.f32.f16.f16.f32 "
        "{%0,%1,%2,%3}, {%4,%5,%6,%7}, {%8,%9}, {%0,%1,%2,%3};"
        : "+f"(d[0]), "+f"(d[1]), "+f"(d[2]), "+f"(d[3])
        : "r"(a[0]), "r"(a[1]), "r"(a[2]), "r"(a[3]), "r"(b[0]), "r"(b[1]));
}
DEV_INLINE void cp16(const void* dst, const void* src) {
    uint32_t a = (uint32_t)__cvta_generic_to_shared(dst);
    asm volatile("cp.async.ca.shared.global [%0], [%1], 16;" :: "r"(a), "l"(src));
}
DEV_INLINE void ldsm4(uint32_t* r, uint32_t addr) {
    asm volatile("ldmatrix.sync.aligned.m8n8.x4.shared.b16 {%0,%1,%2,%3}, [%4];"
        : "=r"(r[0]), "=r"(r[1]), "=r"(r[2]), "=r"(r[3]) : "r"(addr));
}
DEV_INLINE void ldsm4t(uint32_t* r, uint32_t addr) {
    asm volatile("ldmatrix.sync.aligned.m8n8.x4.trans.shared.b16 {%0,%1,%2,%3}, [%4];"
        : "=r"(r[0]), "=r"(r[1]), "=r"(r[2]), "=r"(r[3]) : "r"(addr));
}
DEV_INLINE uint32_t h2u(__half2 h) { return *(uint32_t*)&h; }

// ---- weight prep: d' = c*16 + p1*4 + p2 ; src d = (p1*4+p2)*64 + c ----
__global__ void perm_wqkv_k(const float* __restrict__ w) {
    __shared__ uint32_t sm[32][33];
    int k20 = blockIdx.x * 32, f0 = blockIdx.y * 32;
    int tx = threadIdx.x, ty = threadIdx.y;     // (32, 8)
#pragma unroll
    for (int i = 0; i < 4; i++) {
        int k2l = ty + i * 8;
        int d0 = 2 * (k20 + k2l), d1 = d0 + 1;
        int s0 = (d0 & 15) * 64 + (d0 >> 4);
        int s1 = (d1 & 15) * 64 + (d1 >> 4);
        sm[k2l][tx] = h2u(__floats2half2_rn(w[(size_t)s0 * QKVD + f0 + tx],
                                            w[(size_t)s1 * QKVD + f0 + tx]));
    }
    __syncthreads();
#pragma unroll
    for (int i = 0; i < 4; i++) {
        int fl = ty + i * 8;
        g_wqkv[(size_t)(f0 + fl) * (TOKD / 2) + k20 + tx] = sm[tx][fl];
    }
}
__global__ void perm_wout_k(const float* __restrict__ w, const float* __restrict__ b) {
    __shared__ uint32_t sm[32][33];
    int e20 = blockIdx.x * 32, d0 = blockIdx.y * 32;
    int tx = threadIdx.x, ty = threadIdx.y;     // (32, 8)
#pragma unroll
    for (int i = 0; i < 4; i++) {
        int e2l = ty + i * 8;
        int e = 2 * (e20 + e2l);
        sm[e2l][tx] = h2u(__floats2half2_rn(w[(size_t)e * TOKD + d0 + tx],
                                            w[(size_t)(e + 1) * TOKD + d0 + tx]));
    }
    __syncthreads();
#pragma unroll
    for (int i = 0; i < 4; i++) {
        int dl = ty + i * 8;
        int d = d0 + dl;
        int dp = (d & 63) * 16 + (d >> 6);
        g_wout[(size_t)dp * (INNERD / 2) + e20 + tx] = sm[tx][dl];
    }
    if (blockIdx.x == 0 && ty == 0) {
        int d = d0 + tx;
        g_bias[(d & 63) * 16 + (d >> 6)] = b[d];
    }
}

// ---- gather: x[b,c,h,w] -> g_tokens[win*64+t][d'] (fp16) ----
__global__ void gather_k(const float* __restrict__ x) {
    int blk = blockIdx.x;
    int b = blk >> 8, h = blk & 255;
    int tid = threadIdx.x;               // 256
    int w4 = tid & 63, c0 = tid >> 6;
    int h1 = h >> 5, hh = h & 31, nh_i = hh >> 2, p1 = hh & 3;
    int w1 = w4 >> 3, nw_j = w4 & 7;
    int win = b * 64 + h1 * 8 + w1;
    int t = nh_i * 8 + nw_j;
    size_t drow = ((size_t)win * 64 + t) * TOKD + p1 * 4;
    size_t sbase = (((size_t)b * 64) * 256 + h) * 256 + w4 * 4;
#pragma unroll
    for (int i = 0; i < 16; i++) {
        int c = c0 * 16 + i;
        float4 v = *(const float4*)&x[sbase + (size_t)c * 65536];
        uint2 o;
        o.x = h2u(__floats2half2_rn(v.x, v.y));
        o.y = h2u(__floats2half2_rn(v.z, v.w));
        *(uint2*)&g_tokens[drow + (size_t)c * 16] = o;
    }
}

// ---- fp16 GEMM: 128x128 CTA, 2x2 warps of 64x64, 4-stage K32 pipeline ----
// stage block (20480 B): A [128][40] half (10240) | B [128][20] u32 (10240)
constexpr int STG = 20480;
constexpr int GEMM_SMEM = 4 * STG;   // 81920
template<int K, int N, int MODE>
__global__ void __launch_bounds__(128, 2) gemm_fp16_k(float* __restrict__ outp) {
    extern __shared__ char smem_raw[];
    const uint32_t sb = (uint32_t)__cvta_generic_to_shared(smem_raw);

    const __half* A = (MODE == 0) ? g_tokens : g_o;
    const uint32_t* Bp = (MODE == 0) ? g_wqkv : g_wout;
    constexpr int K2 = K / 2;

    const int tid = threadIdx.x, warp = tid >> 5, lane = tid & 31;
    const int wm = warp >> 1, wn = warp & 1;
    const int tm = blockIdx.y * 128, tn = blockIdx.x * 128;
    const int r0 = lane >> 2;

    float acc[4][8][4];
#pragma unroll
    for (int mi = 0; mi < 4; mi++)
#pragma unroll
        for (int ni = 0; ni < 8; ni++)
#pragma unroll
            for (int j = 0; j < 4; j++) acc[mi][ni][j] = 0.f;

    constexpr int NS = K / 32;
    const int lr = tid >> 2, lc = tid & 3;

    auto load_stage = [&](int kt) {
        const int st = kt & 3;
        const int k0 = kt * 32, k20 = kt * 16;
        __half* As = (__half*)(smem_raw + st * STG);
        uint32_t* Bs = (uint32_t*)(smem_raw + st * STG + 10240);
        cp16(&As[lr * 40 + lc * 8], &A[(size_t)(tm + lr) * K + k0 + lc * 8]);
        cp16(&As[(lr + 32) * 40 + lc * 8], &A[(size_t)(tm + lr + 32) * K + k0 + lc * 8]);
        cp16(&As[(lr + 64) * 40 + lc * 8], &A[(size_t)(tm + lr + 64) * K + k0 + lc * 8]);
        cp16(&As[(lr + 96) * 40 + lc * 8], &A[(size_t)(tm + lr + 96) * K + k0 + lc * 8]);
        cp16(&Bs[lr * 20 + lc * 4], &Bp[(size_t)(tn + lr) * K2 + k20 + lc * 4]);
        cp16(&Bs[(lr + 32) * 20 + lc * 4], &Bp[(size_t)(tn + lr + 32) * K2 + k20 + lc * 4]);
        cp16(&Bs[(lr + 64) * 20 + lc * 4], &Bp[(size_t)(tn + lr + 64) * K2 + k20 + lc * 4]);
        cp16(&Bs[(lr + 96) * 20 + lc * 4], &Bp[(size_t)(tn + lr + 96) * K2 + k20 + lc * 4]);
        asm volatile("cp.async.commit_group;");
    };

    load_stage(0); load_stage(1); load_stage(2);

    const uint32_t a_lane = (wm * 64 + (lane & 15)) * 80 + (lane >> 4) * 16;
    const uint32_t b_lane = 10240 + (wn * 64 + (lane >> 4) * 8 + (lane & 7)) * 80
                          + ((lane >> 3) & 1) * 16;

    for (int kt = 0; kt < NS; kt++) {
        asm volatile("cp.async.wait_group 2;");
        __syncthreads();
        if (kt + 3 < NS) load_stage(kt + 3);
        const uint32_t stb = sb + (kt & 3) * STG;
        const uint32_t abuf = stb + a_lane;
        const uint32_t bbuf = stb + b_lane;
#pragma unroll
        for (int ks = 0; ks < 2; ks++) {
            uint32_t a[4][4], bq[8][2];
#pragma unroll
            for (int mi = 0; mi < 4; mi++)
                ldsm4(a[mi], abuf + mi * 1280 + ks * 32);
#pragma unroll
            for (int p = 0; p < 4; p++) {
                uint32_t t4[4];
                ldsm4(t4, bbuf + p * 1280 + ks * 32);
                bq[2 * p][0] = t4[0]; bq[2 * p][1] = t4[1];
                bq[2 * p + 1][0] = t4[2]; bq[2 * p + 1][1] = t4[3];
            }
#pragma unroll
            for (int mi = 0; mi < 4; mi++)
#pragma unroll
                for (int ni = 0; ni < 8; ni++)
                    mma16(acc[mi][ni], a[mi], bq[ni]);
        }
    }
    const int c2 = (lane & 3) * 2;
#pragma unroll
    for (int mi = 0; mi < 4; mi++) {
#pragma unroll
        for (int ni = 0; ni < 8; ni++) {
            int row = tm + wm * 64 + mi * 16 + r0;
            int col = tn + wn * 64 + ni * 8 + c2;
            if (MODE == 0) {
                *(uint32_t*)&g_qkv[(size_t)row * N + col] =
                    h2u(__floats2half2_rn(acc[mi][ni][0], acc[mi][ni][1]));
                *(uint32_t*)&g_qkv[(size_t)(row + 8) * N + col] =
                    h2u(__floats2half2_rn(acc[mi][ni][2], acc[mi][ni][3]));
            } else {
                int win = row >> 6, t = row & 63;
                int b = win >> 6, rem = win & 63;
                size_t cterm = (size_t)(col >> 4) << 16;
                float b0 = g_bias[col], b1 = g_bias[col + 1];
                size_t xr = ((size_t)(b * 64) << 16)
                          + ((size_t)(((rem >> 3) << 5) | ((t >> 3) << 2) | ((col >> 2) & 3)) << 8)
                          + (size_t)(((rem & 7) << 5) | ((t & 7) << 2) | (col & 3));
                *(float2*)&outp[xr + cterm] =
                    make_float2(acc[mi][ni][0] + b0, acc[mi][ni][1] + b1);
                int t8 = t + 8;
                size_t xr8 = ((size_t)(b * 64) << 16)
                           + ((size_t)(((rem >> 3) << 5) | ((t8 >> 3) << 2) | ((col >> 2) & 3)) << 8)
                           + (size_t)(((rem & 7) << 5) | ((t8 & 7) << 2) | (col & 3));
                *(float2*)&outp[xr8 + cterm] =
                    make_float2(acc[mi][ni][2] + b0, acc[mi][ni][3] + b1);
            }
        }
    }
}

// ---- attention: CTA = (window, head), 1 warp, tensor-core S and PV ----
__global__ void __launch_bounds__(32) attn_k() {
    __shared__ __half Qs[64 * 72];       // 9216 B, rows stride 144 B
    __shared__ uint32_t Ksm[64 * 36];    // 9216 B, k2-packed, stride 144 B
    __shared__ __half Vs[64 * 72];       // 9216 B
    const int win = blockIdx.y, hd = blockIdx.x, lane = threadIdx.x;
    const __half* base = g_qkv + (size_t)win * 64 * QKVD + hd * 64;
    const __half2 sc = __floats2half2_rn(0.125f, 0.125f);

#pragma unroll
    for (int i = 0; i < 16; i++) {
        int idx = i * 32 + lane;
        int r = idx >> 3, c8 = idx & 7;
        const __half* rp = base + (size_t)r * QKVD;
        uint4 q4 = *(const uint4*)(rp + c8 * 8);
        __half2* qh = (__half2*)&q4;
        qh[0] = __hmul2(qh[0], sc); qh[1] = __hmul2(qh[1], sc);
        qh[2] = __hmul2(qh[2], sc); qh[3] = __hmul2(qh[3], sc);
        *(uint4*)&Qs[r * 72 + c8 * 8] = q4;
        *(uint4*)&Ksm[r * 36 + c8 * 4] = *(const uint4*)(rp + INNERD + c8 * 8);
        *(uint4*)&Vs[r * 72 + c8 * 8] = *(const uint4*)(rp + 2 * INNERD + c8 * 8);
    }
    __syncwarp();

    const uint32_t sbQ = (uint32_t)__cvta_generic_to_shared(Qs);
    const uint32_t sbK = (uint32_t)__cvta_generic_to_shared(Ksm);
    const uint32_t sbV = (uint32_t)__cvta_generic_to_shared(Vs);

    // Q fragments: a[mi][ks][4]
    uint32_t a[4][4][4];
#pragma unroll
    for (int mi = 0; mi < 4; mi++)
#pragma unroll
        for (int ks = 0; ks < 4; ks++)
            ldsm4(a[mi][ks],
                  sbQ + ((mi * 16 + (lane & 15)) * 72 + ks * 16 + (lane >> 4) * 8) * 2);

    // S = Q @ K^T
    float s[4][8][4];
#pragma unroll
    for (int mi = 0; mi < 4; mi++)
#pragma unroll
        for (int ni = 0; ni < 8; ni++)
#pragma unroll
            for (int j = 0; j < 4; j++) s[mi][ni][j] = 0.f;
    const uint32_t kl = sbK + ((lane >> 4) * 8 + (lane & 7)) * 144 + ((lane >> 3) & 1) * 16;
#pragma unroll
    for (int ks = 0; ks < 4; ks++) {
#pragma unroll
        for (int p = 0; p < 4; p++) {
            uint32_t t4[4];
            ldsm4(t4, kl + p * 2304 + ks * 32);
#pragma unroll
            for (int mi = 0; mi < 4; mi++) {
                mma16(s[mi][2 * p], a[mi][ks], t4);
                mma16(s[mi][2 * p + 1], a[mi][ks], t4 + 2);
            }
        }
    }

    // softmax over columns (keys); rows r0 = mi*16 + lane/4, r0+8
    float inv0[4], inv1[4];
#pragma unroll
    for (int mi = 0; mi < 4; mi++) {
        float m0 = -1e30f, m1 = -1e30f;
#pragma unroll
        for (int ni = 0; ni < 8; ni++) {
            m0 = fmaxf(m0, fmaxf(s[mi][ni][0], s[mi][ni][1]));
            m1 = fmaxf(m1, fmaxf(s[mi][ni][2], s[mi][ni][3]));
        }
        m0 = fmaxf(m0, __shfl_xor_sync(0xffffffff, m0, 1));
        m0 = fmaxf(m0, __shfl_xor_sync(0xffffffff, m0, 2));
        m1 = fmaxf(m1, __shfl_xor_sync(0xffffffff, m1, 1));
        m1 = fmaxf(m1, __shfl_xor_sync(0xffffffff, m1, 2));
        float s0 = 0.f, s1 = 0.f;
#pragma unroll
        for (int ni = 0; ni < 8; ni++) {
            s[mi][ni][0] = __expf(s[mi][ni][0] - m0);
            s[mi][ni][1] = __expf(s[mi][ni][1] - m0);
            s[mi][ni][2] = __expf(s[mi][ni][2] - m1);
            s[mi][ni][3] = __expf(s[mi][ni][3] - m1);
            s0 += s[mi][ni][0] + s[mi][ni][1];
            s1 += s[mi][ni][2] + s[mi][ni][3];
        }
        s0 += __shfl_xor_sync(0xffffffff, s0, 1);
        s0 += __shfl_xor_sync(0xffffffff, s0, 2);
        s1 += __shfl_xor_sync(0xffffffff, s1, 1);
        s1 += __shfl_xor_sync(0xffffffff, s1, 2);
        inv0[mi] = 1.f / s0; inv1[mi] = 1.f / s1;
    }

    // P (fp16, unnormalized) as A-fragments: C-layout == A-layout trick
    uint32_t pa[4][4][4];
#pragma unroll
    for (int mi = 0; mi < 4; mi++)
#pragma unroll
        for (int ks = 0; ks < 4; ks++) {
            pa[mi][ks][0] = h2u(__floats2half2_rn(s[mi][2 * ks][0], s[mi][2 * ks][1]));
            pa[mi][ks][1] = h2u(__floats2half2_rn(s[mi][2 * ks][2], s[mi][2 * ks][3]));
            pa[mi][ks][2] = h2u(__floats2half2_rn(s[mi][2 * ks + 1][0], s[mi][2 * ks + 1][1]));
            pa[mi][ks][3] = h2u(__floats2half2_rn(s[mi][2 * ks + 1][2], s[mi][2 * ks + 1][3]));
        }

    // O = P @ V   (V fragments via ldmatrix.trans on [tok][d] layout)
    float o[4][8][4];
#pragma unroll
    for (int mi = 0; mi < 4; mi++)
#pragma unroll
        for (int ni = 0; ni < 8; ni++)
#pragma unroll
            for (int j = 0; j < 4; j++) o[mi][ni][j] = 0.f;
    const uint32_t vl = sbV + ((lane & 15) * 72 + (lane >> 4) * 8) * 2;
#pragma unroll
    for (int ks = 0; ks < 4; ks++) {
#pragma unroll
        for (int nd = 0; nd < 4; nd++) {
            uint32_t t4[4];
            ldsm4t(t4, vl + ks * 2304 + nd * 32);
#pragma unroll
            for (int mi = 0; mi < 4; mi++) {
                mma16(o[mi][2 * nd], pa[mi][ks], t4);
                mma16(o[mi][2 * nd + 1], pa[mi][ks], t4 + 2);
            }
        }
    }

    // store (normalize by row sums)
    __half* ob = g_o + (size_t)win * 64 * INNERD + hd * 64;
#pragma unroll
    for (int mi = 0; mi < 4; mi++) {
        int r = mi * 16 + (lane >> 2);
#pragma unroll
        for (int ni = 0; ni < 8; ni++) {
            int col = ni * 8 + (lane & 3) * 2;
            *(__half2*)&ob[(size_t)r * INNERD + col] =
                __floats2half2_rn(o[mi][ni][0] * inv0[mi], o[mi][ni][1] * inv0[mi]);
            *(__half2*)&ob[(size_t)(r + 8) * INNERD + col] =
                __floats2half2_rn(o[mi][ni][2] * inv1[mi], o[mi][ni][3] * inv1[mi]);
        }
    }
}

extern "C" void kernel_launch(void* const* d_in, const int* in_sizes, int n_in,
                              void* d_out, int out_size) {
    const float* x     = (const float*)d_in[0];
    const float* w_qkv = (const float*)d_in[1];
    const float* w_out = (const float*)d_in[2];
    const float* b_out = (const float*)d_in[3];
    float* out = (float*)d_out;

    cudaFuncSetAttribute(gemm_fp16_k<TOKD, QKVD, 0>,
                         cudaFuncAttributeMaxDynamicSharedMemorySize, GEMM_SMEM);
    cudaFuncSetAttribute(gemm_fp16_k<INNERD, TOKD, 1>,
                         cudaFuncAttributeMaxDynamicSharedMemorySize, GEMM_SMEM);

    perm_wqkv_k<<<dim3(TOKD / 64, QKVD / 32), dim3(32, 8)>>>(w_qkv);
    perm_wout_k<<<dim3(INNERD / 64, TOKD / 32), dim3(32, 8)>>>(w_out, b_out);
    gather_k<<<2048, 256>>>(x);
    gemm_fp16_k<TOKD, QKVD, 0>
        <<<dim3(QKVD / 128, NTOK / 128), 128, GEMM_SMEM>>>(nullptr);
    attn_k<<<dim3(8, 512), 32>>>();
    gemm_fp16_k<INNERD, TOKD, 1>
        <<<dim3(TOKD / 128, NTOK / 128), 128, GEMM_SMEM>>>(out);
}